// round 1
// baseline (speedup 1.0000x reference)
#include <cuda_runtime.h>
#include <math.h>

#define BB   16
#define CC   256
#define HWN  4096
#define KK   4
#define HIDN 512
#define EPS_W 1e-8f
#define LN_EPS 1e-5f
#define SCALE 0.0625f   // C^-0.5 = 1/16

// ---------------- scratch (static device globals; no allocation) ----------------
static __device__ __align__(16) float g_xnl [BB*HWN*CC];   // LN'd input, (b,n,c)
static __device__ __align__(16) float g_slots[BB*KK*CC];
static __device__ __align__(16) float g_qt  [BB*KK*CC];    // scale * Wk^T q
static __device__            float g_qb  [BB*KK];          // scale * q.bk
static __device__ __align__(16) float g_A   [BB*KK*CC];
static __device__            float g_S   [BB*KK];
static __device__ __align__(16) float g_upd [BB*KK*CC];
static __device__ __align__(16) float g_spre[BB*KK*CC];
static __device__ __align__(16) float g_m   [BB*KK*CC];
static __device__ __align__(16) float g_h   [BB*KK*HIDN];

__device__ __forceinline__ float gelu_f(float x) {
    return 0.5f * x * (1.0f + erff(x * 0.70710678118654752f));
}

__device__ __forceinline__ float block_reduce_256(float v, float* red, int tid) {
    red[tid] = v; __syncthreads();
    #pragma unroll
    for (int s = 128; s > 0; s >>= 1) {
        if (tid < s) red[tid] += red[tid + s];
        __syncthreads();
    }
    float r = red[0]; __syncthreads();
    return r;
}

// ---------------- K1: LayerNorm of transposed input: x (b,c,h,w) -> xnl (b,n,c) ----------
// grid 2048 (=16 b * 128 tiles of 32 tokens), block 256
__global__ void __launch_bounds__(256) k_ln_input(const float* __restrict__ x,
                                                  const float* __restrict__ lg,
                                                  const float* __restrict__ lb) {
    __shared__ float sm[CC * 33];      // [c][n] padded
    __shared__ float ps[8][32], pq[8][32];
    __shared__ float mu[32], rs[32];
    int b = blockIdx.x >> 7;
    int tile = blockIdx.x & 127;
    int n0 = tile * 32;
    int tid = threadIdx.x;

    const float* xb = x + ((size_t)b * CC) * HWN + n0;
    #pragma unroll
    for (int it = 0; it < 32; it++) {
        int idx = it * 256 + tid;
        int n = idx & 31, c = idx >> 5;
        sm[c * 33 + n] = xb[(size_t)c * HWN + n];
    }
    __syncthreads();

    int p = tid >> 5, tn = tid & 31;
    float s = 0.f, sq = 0.f;
    #pragma unroll
    for (int cc = 0; cc < 32; cc++) {
        float v = sm[(p * 32 + cc) * 33 + tn];
        s += v; sq += v * v;
    }
    ps[p][tn] = s; pq[p][tn] = sq;
    __syncthreads();
    if (tid < 32) {
        float S = 0.f, Q = 0.f;
        #pragma unroll
        for (int i = 0; i < 8; i++) { S += ps[i][tid]; Q += pq[i][tid]; }
        float m = S * (1.0f / 256.0f);
        float var = Q * (1.0f / 256.0f) - m * m;
        mu[tid] = m;
        rs[tid] = rsqrtf(var + LN_EPS);
    }
    __syncthreads();

    float gc = lg[tid], bc = lb[tid];
    float* out = g_xnl + ((size_t)(b * HWN + n0)) * CC;
    #pragma unroll
    for (int it = 0; it < 32; it++) {
        float v = sm[tid * 33 + it];
        out[(size_t)it * CC + tid] = (v - mu[it]) * rs[it] * gc + bc;
    }
}

// ---------------- K2: init slots ----------------
// grid 64, block 256
__global__ void k_init_slots(const float* __restrict__ smu,
                             const float* __restrict__ slsig,
                             const float* __restrict__ noise) {
    int i = blockIdx.x * 256 + threadIdx.x;
    int c = threadIdx.x;
    g_slots[i] = smu[c] + expf(slsig[c]) * noise[i];
}

// ---------------- K3a: per-slot LN + q + q~ = scale*Wk^T q, zero A/S ----------------
// grid 64 (b*K+k), block 256
__global__ void __launch_bounds__(256) k_slot_qt(const float* __restrict__ lg,
                                                 const float* __restrict__ lb,
                                                 const float* __restrict__ Wq,
                                                 const float* __restrict__ bq,
                                                 const float* __restrict__ Wk,
                                                 const float* __restrict__ bkv) {
    __shared__ __align__(16) float s_s[CC];
    __shared__ float s_q[CC];
    __shared__ float red[CC];
    int bk = blockIdx.x;
    int tid = threadIdx.x;

    float v = g_slots[bk * CC + tid];
    float mean = block_reduce_256(v, red, tid) * (1.0f / 256.0f);
    float dv = v - mean;
    float var = block_reduce_256(dv * dv, red, tid) * (1.0f / 256.0f);
    float rstd = rsqrtf(var + LN_EPS);
    float sv = dv * rstd * lg[tid] + lb[tid];
    s_s[tid] = sv;
    __syncthreads();

    // q_d = s . Wq[d,:] + bq_d
    float acc = bq[tid];
    const float4* wrow = (const float4*)(Wq + (size_t)tid * CC);
    const float4* ss = (const float4*)s_s;
    #pragma unroll 8
    for (int i = 0; i < 64; i++) {
        float4 w = wrow[i], s4 = ss[i];
        acc += w.x * s4.x + w.y * s4.y + w.z * s4.z + w.w * s4.w;
    }
    s_q[tid] = acc;
    float qb = block_reduce_256(acc * bkv[tid], red, tid);  // also syncs s_q

    // q~_c = sum_d q_d * Wk[d,c]
    float accq = 0.f;
    #pragma unroll 4
    for (int d = 0; d < 256; d++) accq += s_q[d] * Wk[(size_t)d * CC + tid];
    g_qt[bk * CC + tid] = accq * SCALE;
    if (tid == 0) {
        g_qb[bk] = qb * SCALE;
        g_S[bk] = 0.f;
    }
    g_A[bk * CC + tid] = 0.f;
}

// ---------------- K3b: streaming attention pass over xnl ----------------
// grid 512 (b*32+tile), block 256 (8 warps, 16 tokens each)
__global__ void __launch_bounds__(256) k_attn() {
    int b = blockIdx.x >> 5;
    int tile = blockIdx.x & 31;
    int warp = threadIdx.x >> 5;
    int lane = threadIdx.x & 31;

    float4 qr[KK][2];
    float qb[KK];
    #pragma unroll
    for (int k = 0; k < KK; k++) {
        const float4* qp = (const float4*)(g_qt + (b * KK + k) * CC) + lane * 2;
        qr[k][0] = qp[0]; qr[k][1] = qp[1];
        qb[k] = g_qb[b * KK + k];
    }

    float acc[KK][8];
    float ssum[KK];
    #pragma unroll
    for (int k = 0; k < KK; k++) {
        ssum[k] = 0.f;
        #pragma unroll
        for (int j = 0; j < 8; j++) acc[k][j] = 0.f;
    }

    #pragma unroll 2
    for (int i = 0; i < 16; i++) {
        int n = tile * 128 + i * 8 + warp;
        const float4* xp = (const float4*)(g_xnl + ((size_t)(b * HWN + n)) * CC) + lane * 2;
        float4 x0 = xp[0], x1 = xp[1];
        float l[KK];
        #pragma unroll
        for (int k = 0; k < KK; k++) {
            float d = x0.x * qr[k][0].x + x0.y * qr[k][0].y + x0.z * qr[k][0].z + x0.w * qr[k][0].w
                    + x1.x * qr[k][1].x + x1.y * qr[k][1].y + x1.z * qr[k][1].z + x1.w * qr[k][1].w;
            #pragma unroll
            for (int off = 16; off; off >>= 1) d += __shfl_xor_sync(0xffffffffu, d, off);
            l[k] = d + qb[k];
        }
        float mx = fmaxf(fmaxf(l[0], l[1]), fmaxf(l[2], l[3]));
        float e0 = __expf(l[0] - mx), e1 = __expf(l[1] - mx);
        float e2 = __expf(l[2] - mx), e3 = __expf(l[3] - mx);
        float inv = __fdividef(1.0f, e0 + e1 + e2 + e3);
        float a[KK] = {e0 * inv, e1 * inv, e2 * inv, e3 * inv};
        #pragma unroll
        for (int k = 0; k < KK; k++) {
            ssum[k] += a[k];
            acc[k][0] += a[k] * x0.x; acc[k][1] += a[k] * x0.y;
            acc[k][2] += a[k] * x0.z; acc[k][3] += a[k] * x0.w;
            acc[k][4] += a[k] * x1.x; acc[k][5] += a[k] * x1.y;
            acc[k][6] += a[k] * x1.z; acc[k][7] += a[k] * x1.w;
        }
    }

    #pragma unroll
    for (int k = 0; k < KK; k++) {
        float* Ap = g_A + (b * KK + k) * CC + lane * 8;
        #pragma unroll
        for (int j = 0; j < 8; j++) atomicAdd(Ap + j, acc[k][j]);
        if (lane == 0) atomicAdd(&g_S[b * KK + k], ssum[k]);
    }
}

// ---------------- K3c-1: updates = (A/(S+eps)) @ Wv^T + (S/(S+eps)) bv ----------------
// grid 32 (8 d's each), block 256
__global__ void __launch_bounds__(256) k_upd(const float* __restrict__ Wv,
                                             const float* __restrict__ bv) {
    __shared__ __align__(16) float sw[8 * 260];
    int d0 = blockIdx.x * 8;
    int tid = threadIdx.x;
    #pragma unroll
    for (int it = 0; it < 8; it++) {
        int idx = it * 256 + tid;
        sw[(idx >> 8) * 260 + (idx & 255)] = Wv[(size_t)d0 * CC + idx];
    }
    __syncthreads();
    #pragma unroll
    for (int rep = 0; rep < 2; rep++) {
        int p = rep * 256 + tid;
        int row = p >> 3, dl = p & 7;
        float S = g_S[row];
        float inv = 1.0f / (S + EPS_W);
        const float4* a4 = (const float4*)(g_A + row * CC);
        const float4* w4 = (const float4*)(sw + dl * 260);
        float acc = 0.f;
        #pragma unroll 8
        for (int i = 0; i < 64; i++) {
            float4 a = a4[i], w = w4[i];
            acc += a.x * w.x + a.y * w.y + a.z * w.z + a.w * w.w;
        }
        g_upd[row * CC + d0 + dl] = acc * inv + (S * inv) * bv[d0 + dl];
    }
}

// ---------------- K3c-2: spre = [prev,upd] @ Wu^T + bu + prev ----------------
// grid 32, block 256
__global__ void __launch_bounds__(256) k_spre(const float* __restrict__ Wu,
                                              const float* __restrict__ bu) {
    __shared__ __align__(16) float sw[8 * 516];
    int d0 = blockIdx.x * 8;
    int tid = threadIdx.x;
    #pragma unroll
    for (int it = 0; it < 16; it++) {
        int idx = it * 256 + tid;
        sw[(idx >> 9) * 516 + (idx & 511)] = Wu[(size_t)d0 * 512 + idx];
    }
    __syncthreads();
    #pragma unroll
    for (int rep = 0; rep < 2; rep++) {
        int p = rep * 256 + tid;
        int row = p >> 3, dl = p & 7;
        int d = d0 + dl;
        const float4* pr = (const float4*)(g_slots + row * CC);
        const float4* up = (const float4*)(g_upd + row * CC);
        const float4* w0 = (const float4*)(sw + dl * 516);
        const float4* w1 = (const float4*)(sw + dl * 516 + 256);
        float acc = bu[d] + g_slots[row * CC + d];
        #pragma unroll 8
        for (int i = 0; i < 64; i++) {
            float4 a = pr[i], w = w0[i];
            acc += a.x * w.x + a.y * w.y + a.z * w.z + a.w * w.w;
            float4 u = up[i], v = w1[i];
            acc += u.x * v.x + u.y * v.y + u.z * v.z + u.w * v.w;
        }
        g_spre[row * CC + d] = acc;
    }
}

// ---------------- K3c-3: m = LN(spre) with ln_mlp ----------------
// grid 64, block 256
__global__ void __launch_bounds__(256) k_mlp_ln(const float* __restrict__ lg,
                                                const float* __restrict__ lb) {
    __shared__ float red[CC];
    int row = blockIdx.x, tid = threadIdx.x;
    float v = g_spre[row * CC + tid];
    float mean = block_reduce_256(v, red, tid) * (1.0f / 256.0f);
    float dv = v - mean;
    float var = block_reduce_256(dv * dv, red, tid) * (1.0f / 256.0f);
    float rstd = rsqrtf(var + LN_EPS);
    g_m[row * CC + tid] = dv * rstd * lg[tid] + lb[tid];
}

// ---------------- K3c-4: h = gelu(m @ W1^T + b1) ----------------
// grid 64 (8 j's each), block 256
__global__ void __launch_bounds__(256) k_hid(const float* __restrict__ W1,
                                             const float* __restrict__ b1) {
    __shared__ __align__(16) float sw[8 * 260];
    int j0 = blockIdx.x * 8;
    int tid = threadIdx.x;
    #pragma unroll
    for (int it = 0; it < 8; it++) {
        int idx = it * 256 + tid;
        sw[(idx >> 8) * 260 + (idx & 255)] = W1[(size_t)j0 * CC + idx];
    }
    __syncthreads();
    #pragma unroll
    for (int rep = 0; rep < 2; rep++) {
        int p = rep * 256 + tid;
        int row = p >> 3, jl = p & 7;
        const float4* m4 = (const float4*)(g_m + row * CC);
        const float4* w4 = (const float4*)(sw + jl * 260);
        float acc = b1[j0 + jl];
        #pragma unroll 8
        for (int i = 0; i < 64; i++) {
            float4 a = m4[i], w = w4[i];
            acc += a.x * w.x + a.y * w.y + a.z * w.z + a.w * w.w;
        }
        g_h[row * HIDN + j0 + jl] = gelu_f(acc);
    }
}

// ---------------- K3c-5: slots = spre + h @ W2^T + b2 ----------------
// grid 32, block 256
__global__ void __launch_bounds__(256) k_outp(const float* __restrict__ W2,
                                              const float* __restrict__ b2) {
    __shared__ __align__(16) float sw[8 * 516];
    int d0 = blockIdx.x * 8;
    int tid = threadIdx.x;
    #pragma unroll
    for (int it = 0; it < 16; it++) {
        int idx = it * 256 + tid;
        sw[(idx >> 9) * 516 + (idx & 511)] = W2[(size_t)d0 * HIDN + idx];
    }
    __syncthreads();
    #pragma unroll
    for (int rep = 0; rep < 2; rep++) {
        int p = rep * 256 + tid;
        int row = p >> 3, dl = p & 7;
        int d = d0 + dl;
        const float4* h4 = (const float4*)(g_h + row * HIDN);
        const float4* w4 = (const float4*)(sw + dl * 516);
        float acc = b2[d] + g_spre[row * CC + d];
        #pragma unroll 8
        for (int i = 0; i < 128; i++) {
            float4 a = h4[i], w = w4[i];
            acc += a.x * w.x + a.y * w.y + a.z * w.z + a.w * w.w;
        }
        g_slots[row * CC + d] = acc;
    }
}

// ---------------- K4: final head + output write ----------------
// grid 64, block 128
__global__ void __launch_bounds__(128) k_final(const float* __restrict__ We1,
                                               const float* __restrict__ be1,
                                               const float* __restrict__ We2,
                                               const float* __restrict__ be2,
                                               float* __restrict__ out) {
    __shared__ __align__(16) float s[CC];
    __shared__ float red[128];
    int row = blockIdx.x, tid = threadIdx.x;
    float v0 = g_slots[row * CC + tid];
    float v1 = g_slots[row * CC + tid + 128];
    s[tid] = v0; s[tid + 128] = v1;
    out[row * CC + tid] = v0;
    out[row * CC + tid + 128] = v1;
    __syncthreads();

    const float4* w4 = (const float4*)(We1 + (size_t)tid * CC);
    const float4* s4 = (const float4*)s;
    float acc = be1[tid];
    #pragma unroll 8
    for (int i = 0; i < 64; i++) {
        float4 a = s4[i], w = w4[i];
        acc += a.x * w.x + a.y * w.y + a.z * w.z + a.w * w.w;
    }
    float e = gelu_f(acc);
    red[tid] = e * We2[tid];
    __syncthreads();
    #pragma unroll
    for (int st = 64; st > 0; st >>= 1) {
        if (tid < st) red[tid] += red[tid + st];
        __syncthreads();
    }
    if (tid == 0) {
        float z = red[0] + be2[0];
        out[BB * KK * CC + row] = 1.0f / (1.0f + expf(-z));
    }
}

// ---------------- host ----------------
extern "C" void kernel_launch(void* const* d_in, const int* in_sizes, int n_in,
                              void* d_out, int out_size) {
    const float* x        = (const float*)d_in[0];
    const float* noise    = (const float*)d_in[1];
    const float* slot_mu  = (const float*)d_in[2];
    const float* slot_ls  = (const float*)d_in[3];
    const float* ln_in_g  = (const float*)d_in[4];
    const float* ln_in_b  = (const float*)d_in[5];
    const float* ln_sl_g  = (const float*)d_in[6];
    const float* ln_sl_b  = (const float*)d_in[7];
    const float* ln_mlp_g = (const float*)d_in[8];
    const float* ln_mlp_b = (const float*)d_in[9];
    const float* Wq = (const float*)d_in[10];
    const float* bq = (const float*)d_in[11];
    const float* Wk = (const float*)d_in[12];
    const float* bk = (const float*)d_in[13];
    const float* Wv = (const float*)d_in[14];
    const float* bv = (const float*)d_in[15];
    const float* Wu = (const float*)d_in[16];
    const float* bu = (const float*)d_in[17];
    const float* W1 = (const float*)d_in[18];
    const float* b1 = (const float*)d_in[19];
    const float* W2 = (const float*)d_in[20];
    const float* b2 = (const float*)d_in[21];
    const float* We1 = (const float*)d_in[22];
    const float* be1 = (const float*)d_in[23];
    const float* We2 = (const float*)d_in[24];
    const float* be2 = (const float*)d_in[25];
    float* out = (float*)d_out;

    k_ln_input<<<2048, 256>>>(x, ln_in_g, ln_in_b);
    k_init_slots<<<64, 256>>>(slot_mu, slot_ls, noise);

    for (int it = 0; it < 3; it++) {
        k_slot_qt<<<64, 256>>>(ln_sl_g, ln_sl_b, Wq, bq, Wk, bk);
        k_attn<<<512, 256>>>();
        k_upd<<<32, 256>>>(Wv, bv);
        k_spre<<<32, 256>>>(Wu, bu);
        k_mlp_ln<<<64, 256>>>(ln_mlp_g, ln_mlp_b);
        k_hid<<<64, 256>>>(W1, b1);
        k_outp<<<32, 256>>>(W2, b2);
    }

    k_final<<<64, 128>>>(We1, be1, We2, be2, out);
}

// round 2
// speedup vs baseline: 1.6458x; 1.6458x over previous
#include <cuda_runtime.h>
#include <math.h>

#define BB   16
#define CC   256
#define HWN  4096
#define KK   4
#define HIDN 512
#define EPS_W 1e-8f
#define LN_EPS 1e-5f
#define SCALE 0.0625f   // C^-0.5 = 1/16

// ---------------- scratch (static device globals; no allocation) ----------------
static __device__ __align__(16) float g_xnl [BB*HWN*CC];   // LN'd input, (b,n,c)
static __device__ __align__(16) float g_slots[BB*KK*CC];
static __device__ __align__(16) float g_qt  [BB*KK*CC];    // scale * Wk^T q
static __device__            float g_qb  [BB*KK];          // scale * q.bk
static __device__ __align__(16) float g_A   [BB*KK*CC];
static __device__            float g_S   [BB*KK];
static __device__ __align__(16) float g_spre[BB*KK*CC];
static __device__ __align__(16) float g_h   [BB*KK*HIDN];
static __device__ __align__(16) float g_Wvu [CC*CC];       // Wu2 @ Wv  (256x256)
static __device__            float g_bvu [CC];             // Wu2 @ bv

__device__ __forceinline__ float gelu_f(float x) {
    return 0.5f * x * (1.0f + erff(x * 0.70710678118654752f));
}

__device__ __forceinline__ float block_reduce_256(float v, float* red, int tid) {
    red[tid] = v; __syncthreads();
    #pragma unroll
    for (int s = 128; s > 0; s >>= 1) {
        if (tid < s) red[tid] += red[tid + s];
        __syncthreads();
    }
    float r = red[0]; __syncthreads();
    return r;
}

// Reduce 4 per-lane partials across the warp; return full sums to all lanes.
// 2 butterfly levels on 4 vals (8 shfl) -> per-group select -> 3 levels (3 shfl)
// -> 4 broadcasts. Chain depth ~6 shfl instead of 5 serialized trees.
__device__ __forceinline__ void reduce4_warp(float d0, float d1, float d2, float d3,
                                             float& r0, float& r1, float& r2, float& r3,
                                             int lane) {
    d0 += __shfl_xor_sync(0xffffffffu, d0, 16);
    d1 += __shfl_xor_sync(0xffffffffu, d1, 16);
    d2 += __shfl_xor_sync(0xffffffffu, d2, 16);
    d3 += __shfl_xor_sync(0xffffffffu, d3, 16);
    d0 += __shfl_xor_sync(0xffffffffu, d0, 8);
    d1 += __shfl_xor_sync(0xffffffffu, d1, 8);
    d2 += __shfl_xor_sync(0xffffffffu, d2, 8);
    d3 += __shfl_xor_sync(0xffffffffu, d3, 8);
    int g = lane >> 3;
    float w = (g == 0) ? d0 : ((g == 1) ? d1 : ((g == 2) ? d2 : d3));
    w += __shfl_xor_sync(0xffffffffu, w, 4);
    w += __shfl_xor_sync(0xffffffffu, w, 2);
    w += __shfl_xor_sync(0xffffffffu, w, 1);
    r0 = __shfl_sync(0xffffffffu, w, 0);
    r1 = __shfl_sync(0xffffffffu, w, 8);
    r2 = __shfl_sync(0xffffffffu, w, 16);
    r3 = __shfl_sync(0xffffffffu, w, 24);
}

// ---------------- K0: one-time precompute Wvu = Wu2 @ Wv, bvu = Wu2 @ bv ----------
// grid 64 (4 d-rows each), block 256
__global__ void __launch_bounds__(256) k_prep(const float* __restrict__ Wu,
                                              const float* __restrict__ Wv,
                                              const float* __restrict__ bv) {
    __shared__ __align__(16) float sWv[32 * 260];
    __shared__ __align__(16) float wu2s[CC * 4];   // [e][dl]
    int d0 = blockIdx.x * 4;
    int tid = threadIdx.x;

    for (int idx = tid; idx < CC * 4; idx += 256) {
        int dl = idx & 3, e = idx >> 2;
        wu2s[idx] = Wu[(size_t)(d0 + dl) * 512 + 256 + e];
    }
    __syncthreads();

    float a0 = 0.f, a1 = 0.f, a2 = 0.f, a3 = 0.f;
    for (int ch = 0; ch < 8; ch++) {
        #pragma unroll
        for (int it = 0; it < 32; it++)
            sWv[it * 260 + tid] = Wv[(size_t)(ch * 32 + it) * CC + tid];
        __syncthreads();
        #pragma unroll
        for (int el = 0; el < 32; el++) {
            float x = sWv[el * 260 + tid];
            float4 w = *(const float4*)&wu2s[(ch * 32 + el) * 4];
            a0 += w.x * x; a1 += w.y * x; a2 += w.z * x; a3 += w.w * x;
        }
        __syncthreads();
    }
    g_Wvu[(size_t)(d0 + 0) * CC + tid] = a0;
    g_Wvu[(size_t)(d0 + 1) * CC + tid] = a1;
    g_Wvu[(size_t)(d0 + 2) * CC + tid] = a2;
    g_Wvu[(size_t)(d0 + 3) * CC + tid] = a3;

    if (tid < 4) {
        float s = 0.f;
        for (int e = 0; e < CC; e++)
            s += Wu[(size_t)(d0 + tid) * 512 + 256 + e] * bv[e];
        g_bvu[d0 + tid] = s;
    }
}

// ---------------- K1: LayerNorm of transposed input: x (b,c,h,w) -> xnl (b,n,c) ----------
// grid 2048, block 256
__global__ void __launch_bounds__(256) k_ln_input(const float* __restrict__ x,
                                                  const float* __restrict__ lg,
                                                  const float* __restrict__ lb) {
    __shared__ float sm[CC * 33];
    __shared__ float ps[8][32], pq[8][32];
    __shared__ float mu[32], rs[32];
    int b = blockIdx.x >> 7;
    int tile = blockIdx.x & 127;
    int n0 = tile * 32;
    int tid = threadIdx.x;

    const float* xb = x + ((size_t)b * CC) * HWN + n0;
    #pragma unroll
    for (int it = 0; it < 32; it++) {
        int idx = it * 256 + tid;
        int n = idx & 31, c = idx >> 5;
        sm[c * 33 + n] = xb[(size_t)c * HWN + n];
    }
    __syncthreads();

    int p = tid >> 5, tn = tid & 31;
    float s = 0.f, sq = 0.f;
    #pragma unroll
    for (int cc = 0; cc < 32; cc++) {
        float v = sm[(p * 32 + cc) * 33 + tn];
        s += v; sq += v * v;
    }
    ps[p][tn] = s; pq[p][tn] = sq;
    __syncthreads();
    if (tid < 32) {
        float S = 0.f, Q = 0.f;
        #pragma unroll
        for (int i = 0; i < 8; i++) { S += ps[i][tid]; Q += pq[i][tid]; }
        float m = S * (1.0f / 256.0f);
        float var = Q * (1.0f / 256.0f) - m * m;
        mu[tid] = m;
        rs[tid] = rsqrtf(var + LN_EPS);
    }
    __syncthreads();

    float gc = lg[tid], bc = lb[tid];
    float* out = g_xnl + ((size_t)(b * HWN + n0)) * CC;
    #pragma unroll
    for (int it = 0; it < 32; it++) {
        float v = sm[tid * 33 + it];
        out[(size_t)it * CC + tid] = (v - mu[it]) * rs[it] * gc + bc;
    }
}

// ---------------- K2: init slots ----------------
__global__ void k_init_slots(const float* __restrict__ smu,
                             const float* __restrict__ slsig,
                             const float* __restrict__ noise) {
    int i = blockIdx.x * 256 + threadIdx.x;
    int c = threadIdx.x;
    g_slots[i] = smu[c] + expf(slsig[c]) * noise[i];
}

// ---------------- K3a: per-slot LN + q + qt = scale*Wk^T q; zero A/S ----------------
// grid 64 (b*K+k), block 256
__global__ void __launch_bounds__(256) k_slot_qt(const float* __restrict__ lg,
                                                 const float* __restrict__ lb,
                                                 const float* __restrict__ Wq,
                                                 const float* __restrict__ bq,
                                                 const float* __restrict__ Wk,
                                                 const float* __restrict__ bkv) {
    __shared__ __align__(16) float s_s[CC];
    __shared__ float s_q[CC];
    __shared__ float red[CC];
    int row = blockIdx.x;
    int tid = threadIdx.x;
    int warp = tid >> 5, lane = tid & 31;

    float v = g_slots[row * CC + tid];
    float mean = block_reduce_256(v, red, tid) * (1.0f / 256.0f);
    float dv = v - mean;
    float var = block_reduce_256(dv * dv, red, tid) * (1.0f / 256.0f);
    float rstd = rsqrtf(var + LN_EPS);
    s_s[tid] = dv * rstd * lg[tid] + lb[tid];
    __syncthreads();

    // q GEMV: warp w computes rows d = w*32 .. w*32+31, coalesced row reads
    const float4* s4 = (const float4*)s_s + lane * 2;
    float4 sA = s4[0], sB = s4[1];
    #pragma unroll 4
    for (int i = 0; i < 32; i++) {
        int d = warp * 32 + i;
        const float4* wr = (const float4*)(Wq + (size_t)d * CC) + lane * 2;
        float4 w0 = wr[0], w1 = wr[1];
        float pt = w0.x * sA.x + w0.y * sA.y + w0.z * sA.z + w0.w * sA.w
                 + w1.x * sB.x + w1.y * sB.y + w1.z * sB.z + w1.w * sB.w;
        #pragma unroll
        for (int off = 16; off; off >>= 1) pt += __shfl_xor_sync(0xffffffffu, pt, off);
        if (lane == i) s_q[d] = pt + bq[d];
    }
    __syncthreads();

    float qv = s_q[tid];
    float qb = block_reduce_256(qv * bkv[tid], red, tid);

    // qt_c = sum_d q_d * Wk[d,c]   (coalesced along c, broadcast q from smem)
    float accq = 0.f;
    #pragma unroll 8
    for (int d = 0; d < 256; d++) accq += s_q[d] * Wk[(size_t)d * CC + tid];
    g_qt[row * CC + tid] = accq * SCALE;
    if (tid == 0) {
        g_qb[row] = qb * SCALE;
        g_S[row] = 0.f;
    }
    g_A[row * CC + tid] = 0.f;
}

// ---------------- K3b: streaming attention pass over xnl ----------------
// grid 512 (b*32+tile of 128 tokens), block 256; warp: 16 tokens, 4 in flight
__global__ void __launch_bounds__(256, 2) k_attn() {
    __shared__ __align__(16) float racc[8][KK][CC];
    __shared__ float racs[8][KK];
    int b = blockIdx.x >> 5;
    int tile = blockIdx.x & 31;
    int warp = threadIdx.x >> 5;
    int lane = threadIdx.x & 31;
    int tid = threadIdx.x;

    float4 qr[KK][2];
    float qbv[KK];
    #pragma unroll
    for (int k = 0; k < KK; k++) {
        const float4* qp = (const float4*)(g_qt + (b * KK + k) * CC) + lane * 2;
        qr[k][0] = qp[0]; qr[k][1] = qp[1];
        qbv[k] = g_qb[b * KK + k];
    }

    float acc[KK][8];
    float ssum[KK];
    #pragma unroll
    for (int k = 0; k < KK; k++) {
        ssum[k] = 0.f;
        #pragma unroll
        for (int j = 0; j < 8; j++) acc[k][j] = 0.f;
    }

    int n0 = tile * 128 + warp * 16;
    const float4* base = (const float4*)(g_xnl + ((size_t)(b * HWN + n0)) * CC) + lane * 2;

    for (int r = 0; r < 4; r++) {
        // load 4 tokens (8 LDG.128 back-to-back)
        float4 xa[4][2];
        #pragma unroll
        for (int t = 0; t < 4; t++) {
            const float4* p = base + (r * 4 + t) * (CC / 4);
            xa[t][0] = p[0];
            xa[t][1] = p[1];
        }
        // per-lane dot partials for 4 tokens x 4 slots
        float part[4][KK];
        #pragma unroll
        for (int t = 0; t < 4; t++) {
            #pragma unroll
            for (int k = 0; k < KK; k++) {
                part[t][k] = xa[t][0].x * qr[k][0].x + xa[t][0].y * qr[k][0].y
                           + xa[t][0].z * qr[k][0].z + xa[t][0].w * qr[k][0].w
                           + xa[t][1].x * qr[k][1].x + xa[t][1].y * qr[k][1].y
                           + xa[t][1].z * qr[k][1].z + xa[t][1].w * qr[k][1].w;
            }
        }
        // reduce + softmax + accumulate, token by token (chains independent)
        #pragma unroll
        for (int t = 0; t < 4; t++) {
            float l0, l1, l2, l3;
            reduce4_warp(part[t][0], part[t][1], part[t][2], part[t][3],
                         l0, l1, l2, l3, lane);
            l0 += qbv[0]; l1 += qbv[1]; l2 += qbv[2]; l3 += qbv[3];
            float mx = fmaxf(fmaxf(l0, l1), fmaxf(l2, l3));
            float e0 = __expf(l0 - mx), e1 = __expf(l1 - mx);
            float e2 = __expf(l2 - mx), e3 = __expf(l3 - mx);
            float inv = __fdividef(1.0f, e0 + e1 + e2 + e3);
            float a[KK] = {e0 * inv, e1 * inv, e2 * inv, e3 * inv};
            #pragma unroll
            for (int k = 0; k < KK; k++) {
                ssum[k] += a[k];
                acc[k][0] += a[k] * xa[t][0].x; acc[k][1] += a[k] * xa[t][0].y;
                acc[k][2] += a[k] * xa[t][0].z; acc[k][3] += a[k] * xa[t][0].w;
                acc[k][4] += a[k] * xa[t][1].x; acc[k][5] += a[k] * xa[t][1].y;
                acc[k][6] += a[k] * xa[t][1].z; acc[k][7] += a[k] * xa[t][1].w;
            }
        }
    }

    // per-warp results -> smem
    #pragma unroll
    for (int k = 0; k < KK; k++) {
        float4* dst = (float4*)&racc[warp][k][lane * 8];
        dst[0] = make_float4(acc[k][0], acc[k][1], acc[k][2], acc[k][3]);
        dst[1] = make_float4(acc[k][4], acc[k][5], acc[k][6], acc[k][7]);
    }
    if (lane == 0) {
        #pragma unroll
        for (int k = 0; k < KK; k++) racs[warp][k] = ssum[k];
    }
    __syncthreads();

    // cross-warp reduce + single atomic set per (k,c)
    #pragma unroll
    for (int k = 0; k < KK; k++) {
        float s = 0.f;
        #pragma unroll
        for (int w = 0; w < 8; w++) s += racc[w][k][tid];
        atomicAdd(&g_A[(b * KK + k) * CC + tid], s);
    }
    if (tid < KK) {
        float s = 0.f;
        #pragma unroll
        for (int w = 0; w < 8; w++) s += racs[w][tid];
        atomicAdd(&g_S[b * KK + tid], s);
    }
}

// ---------------- K3c: spre = prev@Wu1^T + (A/(S+e))@Wvu^T + b*bvu + bu + prev ------
// grid 32 (8 d's each), block 256
__global__ void __launch_bounds__(256) k_spre2(const float* __restrict__ Wu,
                                               const float* __restrict__ bu) {
    __shared__ __align__(16) float sw1[8 * 260];
    __shared__ __align__(16) float swv[8 * 260];
    int d0 = blockIdx.x * 8;
    int tid = threadIdx.x;
    #pragma unroll
    for (int it = 0; it < 8; it++) {
        int idx = it * 256 + tid;
        int r = idx >> 8, c = idx & 255;
        sw1[r * 260 + c] = Wu[(size_t)(d0 + r) * 512 + c];
        swv[r * 260 + c] = g_Wvu[(size_t)(d0 + r) * CC + c];
    }
    __syncthreads();
    #pragma unroll
    for (int rep = 0; rep < 2; rep++) {
        int p = rep * 256 + tid;
        int row = p >> 3, dl = p & 7;
        int d = d0 + dl;
        float S = g_S[row];
        float inv = 1.0f / (S + EPS_W);
        float beta = S * inv;
        const float4* pr = (const float4*)(g_slots + row * CC);
        const float4* a4 = (const float4*)(g_A + row * CC);
        const float4* w1 = (const float4*)(sw1 + dl * 260);
        const float4* wv = (const float4*)(swv + dl * 260);
        float acc = bu[d] + g_slots[row * CC + d] + beta * g_bvu[d];
        float accA = 0.f;
        #pragma unroll 8
        for (int i = 0; i < 64; i++) {
            float4 a = pr[i], w = w1[i];
            acc += a.x * w.x + a.y * w.y + a.z * w.z + a.w * w.w;
            float4 u = a4[i], vv = wv[i];
            accA += u.x * vv.x + u.y * vv.y + u.z * vv.z + u.w * vv.w;
        }
        g_spre[row * CC + d] = acc + inv * accA;
    }
}

// ---------------- K3d: h = gelu(LN(spre) @ W1^T + b1), LN fused ----------------
// grid 64 (8 j's each), block 256
__global__ void __launch_bounds__(256) k_hid(const float* __restrict__ W1,
                                             const float* __restrict__ b1,
                                             const float* __restrict__ lg,
                                             const float* __restrict__ lb) {
    __shared__ __align__(16) float sw[8 * 260];
    __shared__ __align__(16) float slg[CC], slb[CC];
    __shared__ float mu[64], rs[64];
    int j0 = blockIdx.x * 8;
    int tid = threadIdx.x;
    int warp = tid >> 5, lane = tid & 31;

    #pragma unroll
    for (int it = 0; it < 8; it++) {
        int idx = it * 256 + tid;
        sw[(idx >> 8) * 260 + (idx & 255)] = W1[(size_t)j0 * CC + idx];
    }
    slg[tid] = lg[tid];
    slb[tid] = lb[tid];

    // LN stats for all 64 rows: warp w handles rows w*8..w*8+7
    #pragma unroll
    for (int rr = 0; rr < 8; rr++) {
        int row = warp * 8 + rr;
        const float4* pr = (const float4*)(g_spre + row * CC) + lane * 2;
        float4 v0 = pr[0], v1 = pr[1];
        float s = v0.x + v0.y + v0.z + v0.w + v1.x + v1.y + v1.z + v1.w;
        float q = v0.x * v0.x + v0.y * v0.y + v0.z * v0.z + v0.w * v0.w
                + v1.x * v1.x + v1.y * v1.y + v1.z * v1.z + v1.w * v1.w;
        #pragma unroll
        for (int off = 16; off; off >>= 1) {
            s += __shfl_xor_sync(0xffffffffu, s, off);
            q += __shfl_xor_sync(0xffffffffu, q, off);
        }
        if (lane == 0) {
            float m = s * (1.0f / 256.0f);
            mu[row] = m;
            rs[row] = rsqrtf(q * (1.0f / 256.0f) - m * m + LN_EPS);
        }
    }
    __syncthreads();

    #pragma unroll
    for (int rep = 0; rep < 2; rep++) {
        int p = rep * 256 + tid;
        int row = p >> 3, jl = p & 7;
        float m_ = mu[row], r_ = rs[row];
        const float4* sp = (const float4*)(g_spre + row * CC);
        const float4* w4 = (const float4*)(sw + jl * 260);
        const float4* g4 = (const float4*)slg;
        const float4* b4 = (const float4*)slb;
        float acc = b1[j0 + jl];
        #pragma unroll 8
        for (int i = 0; i < 64; i++) {
            float4 v = sp[i], w = w4[i], g = g4[i], bb = b4[i];
            float m0 = (v.x - m_) * r_ * g.x + bb.x;
            float m1 = (v.y - m_) * r_ * g.y + bb.y;
            float m2 = (v.z - m_) * r_ * g.z + bb.z;
            float m3 = (v.w - m_) * r_ * g.w + bb.w;
            acc += m0 * w.x + m1 * w.y + m2 * w.z + m3 * w.w;
        }
        g_h[row * HIDN + j0 + jl] = gelu_f(acc);
    }
}

// ---------------- K3e: slots = spre + h @ W2^T + b2 ----------------
// grid 32, block 256
__global__ void __launch_bounds__(256) k_outp(const float* __restrict__ W2,
                                              const float* __restrict__ b2) {
    __shared__ __align__(16) float sw[8 * 516];
    int d0 = blockIdx.x * 8;
    int tid = threadIdx.x;
    #pragma unroll
    for (int it = 0; it < 16; it++) {
        int idx = it * 256 + tid;
        sw[(idx >> 9) * 516 + (idx & 511)] = W2[(size_t)d0 * HIDN + idx];
    }
    __syncthreads();
    #pragma unroll
    for (int rep = 0; rep < 2; rep++) {
        int p = rep * 256 + tid;
        int row = p >> 3, dl = p & 7;
        int d = d0 + dl;
        const float4* h4 = (const float4*)(g_h + row * HIDN);
        const float4* w4 = (const float4*)(sw + dl * 516);
        float acc = b2[d] + g_spre[row * CC + d];
        #pragma unroll 8
        for (int i = 0; i < 128; i++) {
            float4 a = h4[i], w = w4[i];
            acc += a.x * w.x + a.y * w.y + a.z * w.z + a.w * w.w;
        }
        g_slots[row * CC + d] = acc;
    }
}

// ---------------- K4: final head + output write ----------------
// grid 64, block 128
__global__ void __launch_bounds__(128) k_final(const float* __restrict__ We1,
                                               const float* __restrict__ be1,
                                               const float* __restrict__ We2,
                                               const float* __restrict__ be2,
                                               float* __restrict__ out) {
    __shared__ __align__(16) float s[CC];
    __shared__ float red[128];
    int row = blockIdx.x, tid = threadIdx.x;
    float v0 = g_slots[row * CC + tid];
    float v1 = g_slots[row * CC + tid + 128];
    s[tid] = v0; s[tid + 128] = v1;
    out[row * CC + tid] = v0;
    out[row * CC + tid + 128] = v1;
    __syncthreads();

    const float4* w4 = (const float4*)(We1 + (size_t)tid * CC);
    const float4* s4 = (const float4*)s;
    float acc = be1[tid];
    #pragma unroll 8
    for (int i = 0; i < 64; i++) {
        float4 a = s4[i], w = w4[i];
        acc += a.x * w.x + a.y * w.y + a.z * w.z + a.w * w.w;
    }
    float e = gelu_f(acc);
    red[tid] = e * We2[tid];
    __syncthreads();
    #pragma unroll
    for (int st = 64; st > 0; st >>= 1) {
        if (tid < st) red[tid] += red[tid + st];
        __syncthreads();
    }
    if (tid == 0) {
        float z = red[0] + be2[0];
        out[BB * KK * CC + row] = 1.0f / (1.0f + expf(-z));
    }
}

// ---------------- host ----------------
extern "C" void kernel_launch(void* const* d_in, const int* in_sizes, int n_in,
                              void* d_out, int out_size) {
    const float* x        = (const float*)d_in[0];
    const float* noise    = (const float*)d_in[1];
    const float* slot_mu  = (const float*)d_in[2];
    const float* slot_ls  = (const float*)d_in[3];
    const float* ln_in_g  = (const float*)d_in[4];
    const float* ln_in_b  = (const float*)d_in[5];
    const float* ln_sl_g  = (const float*)d_in[6];
    const float* ln_sl_b  = (const float*)d_in[7];
    const float* ln_mlp_g = (const float*)d_in[8];
    const float* ln_mlp_b = (const float*)d_in[9];
    const float* Wq = (const float*)d_in[10];
    const float* bq = (const float*)d_in[11];
    const float* Wk = (const float*)d_in[12];
    const float* bk = (const float*)d_in[13];
    const float* Wv = (const float*)d_in[14];
    const float* bv = (const float*)d_in[15];
    const float* Wu = (const float*)d_in[16];
    const float* bu = (const float*)d_in[17];
    const float* W1 = (const float*)d_in[18];
    const float* b1 = (const float*)d_in[19];
    const float* W2 = (const float*)d_in[20];
    const float* b2 = (const float*)d_in[21];
    const float* We1 = (const float*)d_in[22];
    const float* be1 = (const float*)d_in[23];
    const float* We2 = (const float*)d_in[24];
    const float* be2 = (const float*)d_in[25];
    float* out = (float*)d_out;

    k_prep<<<64, 256>>>(Wu, Wv, bv);
    k_ln_input<<<2048, 256>>>(x, ln_in_g, ln_in_b);
    k_init_slots<<<64, 256>>>(slot_mu, slot_ls, noise);

    for (int it = 0; it < 3; it++) {
        k_slot_qt<<<64, 256>>>(ln_sl_g, ln_sl_b, Wq, bq, Wk, bk);
        k_attn<<<512, 256>>>();
        k_spre2<<<32, 256>>>(Wu, bu);
        k_hid<<<64, 256>>>(W1, b1, ln_mlp_g, ln_mlp_b);
        k_outp<<<32, 256>>>(W2, b2);
    }

    k_final<<<64, 128>>>(We1, be1, We2, be2, out);
}

// round 3
// speedup vs baseline: 1.6933x; 1.0289x over previous
#include <cuda_runtime.h>
#include <cuda_fp16.h>
#include <math.h>

#define BB   16
#define CC   256
#define HWN  4096
#define KK   4
#define HIDN 512
#define EPS_W 1e-8f
#define LN_EPS 1e-5f
#define SCALE 0.0625f   // C^-0.5 = 1/16

// ---------------- scratch (static device globals; no allocation) ----------------
static __device__ __align__(16) __half g_xnl [BB*HWN*CC];  // LN'd input, (b,n,c), fp16
static __device__ __align__(16) float g_slots[BB*KK*CC];
static __device__ __align__(16) float g_qt  [BB*KK*CC];    // scale * Wk^T q
static __device__            float g_qb  [BB*KK];          // scale * q.bk
static __device__ __align__(16) float g_A   [BB*KK*CC];
static __device__            float g_S   [BB*KK];
static __device__ __align__(16) float g_spre[BB*KK*CC];
static __device__ __align__(16) float g_h   [BB*KK*HIDN];
static __device__ __align__(16) float g_Wvu [CC*CC];       // Wu2 @ Wv
static __device__            float g_bvu [CC];             // Wu2 @ bv
static __device__ __align__(16) float g_Wqk [CC*CC];       // scale * Wk^T Wq, rows=c (output), cols=e (input)
static __device__            float g_qtb [CC];             // scale * Wk^T bq
static __device__ __align__(16) float g_wqbk[CC];          // scale * Wq^T bk
static __device__            float g_bqbk;                 // scale * bq.bk

__device__ __forceinline__ float gelu_f(float x) {
    return 0.5f * x * (1.0f + erff(x * 0.70710678118654752f));
}

__device__ __forceinline__ float block_reduce_256(float v, float* red, int tid) {
    red[tid] = v; __syncthreads();
    #pragma unroll
    for (int s = 128; s > 0; s >>= 1) {
        if (tid < s) red[tid] += red[tid + s];
        __syncthreads();
    }
    float r = red[0]; __syncthreads();
    return r;
}

__device__ __forceinline__ void reduce4_warp(float d0, float d1, float d2, float d3,
                                             float& r0, float& r1, float& r2, float& r3,
                                             int lane) {
    d0 += __shfl_xor_sync(0xffffffffu, d0, 16);
    d1 += __shfl_xor_sync(0xffffffffu, d1, 16);
    d2 += __shfl_xor_sync(0xffffffffu, d2, 16);
    d3 += __shfl_xor_sync(0xffffffffu, d3, 16);
    d0 += __shfl_xor_sync(0xffffffffu, d0, 8);
    d1 += __shfl_xor_sync(0xffffffffu, d1, 8);
    d2 += __shfl_xor_sync(0xffffffffu, d2, 8);
    d3 += __shfl_xor_sync(0xffffffffu, d3, 8);
    int g = lane >> 3;
    float w = (g == 0) ? d0 : ((g == 1) ? d1 : ((g == 2) ? d2 : d3));
    w += __shfl_xor_sync(0xffffffffu, w, 4);
    w += __shfl_xor_sync(0xffffffffu, w, 2);
    w += __shfl_xor_sync(0xffffffffu, w, 1);
    r0 = __shfl_sync(0xffffffffu, w, 0);
    r1 = __shfl_sync(0xffffffffu, w, 8);
    r2 = __shfl_sync(0xffffffffu, w, 16);
    r3 = __shfl_sync(0xffffffffu, w, 24);
}

// ---------------- K0a: precompute Wvu = Wu2 @ Wv, bvu = Wu2 @ bv ----------
__global__ void __launch_bounds__(256) k_prep(const float* __restrict__ Wu,
                                              const float* __restrict__ Wv,
                                              const float* __restrict__ bv) {
    __shared__ __align__(16) float sWv[32 * 260];
    __shared__ __align__(16) float wu2s[CC * 4];
    int d0 = blockIdx.x * 4;
    int tid = threadIdx.x;

    for (int idx = tid; idx < CC * 4; idx += 256) {
        int dl = idx & 3, e = idx >> 2;
        wu2s[idx] = Wu[(size_t)(d0 + dl) * 512 + 256 + e];
    }
    __syncthreads();

    float a0 = 0.f, a1 = 0.f, a2 = 0.f, a3 = 0.f;
    for (int ch = 0; ch < 8; ch++) {
        #pragma unroll
        for (int it = 0; it < 32; it++)
            sWv[it * 260 + tid] = Wv[(size_t)(ch * 32 + it) * CC + tid];
        __syncthreads();
        #pragma unroll
        for (int el = 0; el < 32; el++) {
            float x = sWv[el * 260 + tid];
            float4 w = *(const float4*)&wu2s[(ch * 32 + el) * 4];
            a0 += w.x * x; a1 += w.y * x; a2 += w.z * x; a3 += w.w * x;
        }
        __syncthreads();
    }
    g_Wvu[(size_t)(d0 + 0) * CC + tid] = a0;
    g_Wvu[(size_t)(d0 + 1) * CC + tid] = a1;
    g_Wvu[(size_t)(d0 + 2) * CC + tid] = a2;
    g_Wvu[(size_t)(d0 + 3) * CC + tid] = a3;

    if (tid < 4) {
        float s = 0.f;
        for (int e = 0; e < CC; e++)
            s += Wu[(size_t)(d0 + tid) * 512 + 256 + e] * bv[e];
        g_bvu[d0 + tid] = s;
    }
}

// ---------------- K0b: precompute M = scale*Wk^T Wq, qtb, wqbk, bqbk ----------
// grid 65: blocks 0..63 -> 4 c-rows of M each; block 64 -> wqbk + bqbk
__global__ void __launch_bounds__(256) k_prep2(const float* __restrict__ Wq,
                                               const float* __restrict__ Wk,
                                               const float* __restrict__ bq,
                                               const float* __restrict__ bk) {
    __shared__ __align__(16) float sWq[32 * 260];
    __shared__ float wkc[32][4];
    int tid = threadIdx.x;

    if (blockIdx.x == 64) {
        float s = 0.f;
        #pragma unroll 8
        for (int d = 0; d < CC; d++) s += Wq[(size_t)d * CC + tid] * bk[d];
        g_wqbk[tid] = SCALE * s;
        float* red = sWq;
        float p = block_reduce_256(bq[tid] * bk[tid], red, tid);
        if (tid == 0) g_bqbk = SCALE * p;
        return;
    }

    int c0 = blockIdx.x * 4;
    float a0 = 0.f, a1 = 0.f, a2 = 0.f, a3 = 0.f;
    for (int ch = 0; ch < 8; ch++) {
        #pragma unroll
        for (int it = 0; it < 32; it++)
            sWq[it * 260 + tid] = Wq[(size_t)(ch * 32 + it) * CC + tid];
        if (tid < 128) {
            int dl = tid >> 2, cl = tid & 3;
            wkc[dl][cl] = Wk[(size_t)(ch * 32 + dl) * CC + c0 + cl];
        }
        __syncthreads();
        #pragma unroll
        for (int dl = 0; dl < 32; dl++) {
            float x = sWq[dl * 260 + tid];
            a0 += wkc[dl][0] * x; a1 += wkc[dl][1] * x;
            a2 += wkc[dl][2] * x; a3 += wkc[dl][3] * x;
        }
        __syncthreads();
    }
    g_Wqk[(size_t)(c0 + 0) * CC + tid] = SCALE * a0;
    g_Wqk[(size_t)(c0 + 1) * CC + tid] = SCALE * a1;
    g_Wqk[(size_t)(c0 + 2) * CC + tid] = SCALE * a2;
    g_Wqk[(size_t)(c0 + 3) * CC + tid] = SCALE * a3;

    if (tid < 4) {
        float s = 0.f;
        for (int d = 0; d < CC; d++) s += Wk[(size_t)d * CC + c0 + tid] * bq[d];
        g_qtb[c0 + tid] = SCALE * s;
    }
}

// ---------------- K1: LayerNorm of transposed input -> fp16 xnl (b,n,c) ----------
// grid 2048, block 256
__global__ void __launch_bounds__(256) k_ln_input(const float* __restrict__ x,
                                                  const float* __restrict__ lg,
                                                  const float* __restrict__ lb) {
    __shared__ float sm[CC * 33];
    __shared__ float ps[8][32], pq[8][32];
    __shared__ float mu[32], rs[32];
    int b = blockIdx.x >> 7;
    int tile = blockIdx.x & 127;
    int n0 = tile * 32;
    int tid = threadIdx.x;

    const float* xb = x + ((size_t)b * CC) * HWN + n0;
    #pragma unroll
    for (int it = 0; it < 32; it++) {
        int idx = it * 256 + tid;
        int n = idx & 31, c = idx >> 5;
        sm[c * 33 + n] = xb[(size_t)c * HWN + n];
    }
    __syncthreads();

    int p = tid >> 5, tn = tid & 31;
    float s = 0.f, sq = 0.f;
    #pragma unroll
    for (int cc = 0; cc < 32; cc++) {
        float v = sm[(p * 32 + cc) * 33 + tn];
        s += v; sq += v * v;
    }
    ps[p][tn] = s; pq[p][tn] = sq;
    __syncthreads();
    if (tid < 32) {
        float S = 0.f, Q = 0.f;
        #pragma unroll
        for (int i = 0; i < 8; i++) { S += ps[i][tid]; Q += pq[i][tid]; }
        float m = S * (1.0f / 256.0f);
        float var = Q * (1.0f / 256.0f) - m * m;
        mu[tid] = m;
        rs[tid] = rsqrtf(var + LN_EPS);
    }
    __syncthreads();

    float gc = lg[tid], bc = lb[tid];
    __half* out = g_xnl + ((size_t)(b * HWN + n0)) * CC;
    #pragma unroll
    for (int it = 0; it < 32; it++) {
        float v = sm[tid * 33 + it];
        out[(size_t)it * CC + tid] = __float2half_rn((v - mu[it]) * rs[it] * gc + bc);
    }
}

// ---------------- K2: init slots ----------------
__global__ void k_init_slots(const float* __restrict__ smu,
                             const float* __restrict__ slsig,
                             const float* __restrict__ noise) {
    int i = blockIdx.x * 256 + threadIdx.x;
    int c = threadIdx.x;
    g_slots[i] = smu[c] + expf(slsig[c]) * noise[i];
}

// ---------------- K3a: qt = M@LN(slots) + qtb, qb; zero A/S. grid 32, block 256 ----
__global__ void __launch_bounds__(256) k_qt(const float* __restrict__ lg,
                                            const float* __restrict__ lb) {
    __shared__ __align__(16) float sM[8 * 260];
    __shared__ __align__(16) float sg[CC], sb[CC];
    __shared__ float mu[64], rs[64];
    int c0 = blockIdx.x * 8;
    int tid = threadIdx.x;
    int warp = tid >> 5, lane = tid & 31;

    #pragma unroll
    for (int it = 0; it < 8; it++) {
        int idx = it * 256 + tid;
        sM[(idx >> 8) * 260 + (idx & 255)] = g_Wqk[(size_t)c0 * CC + idx];
    }
    sg[tid] = lg[tid];
    sb[tid] = lb[tid];

    // LN stats: warp w -> rows w*8..w*8+7
    #pragma unroll
    for (int rr = 0; rr < 8; rr++) {
        int row = warp * 8 + rr;
        const float4* pr = (const float4*)(g_slots + row * CC) + lane * 2;
        float4 v0 = pr[0], v1 = pr[1];
        float s = v0.x + v0.y + v0.z + v0.w + v1.x + v1.y + v1.z + v1.w;
        float q = v0.x * v0.x + v0.y * v0.y + v0.z * v0.z + v0.w * v0.w
                + v1.x * v1.x + v1.y * v1.y + v1.z * v1.z + v1.w * v1.w;
        #pragma unroll
        for (int off = 16; off; off >>= 1) {
            s += __shfl_xor_sync(0xffffffffu, s, off);
            q += __shfl_xor_sync(0xffffffffu, q, off);
        }
        if (lane == 0) {
            float m = s * (1.0f / 256.0f);
            mu[row] = m;
            rs[row] = rsqrtf(q * (1.0f / 256.0f) - m * m + LN_EPS);
        }
    }

    // zero A (each block zeroes its 512-float stripe) and S
    g_A[blockIdx.x * 512 + tid] = 0.f;
    g_A[blockIdx.x * 512 + 256 + tid] = 0.f;
    if (blockIdx.x == 0 && tid < BB * KK) g_S[tid] = 0.f;
    __syncthreads();

    // qb (block 0 only): qb[row] = dot(LN(slots[row]), wqbk) + bqbk
    if (blockIdx.x == 0) {
        #pragma unroll
        for (int rr = 0; rr < 8; rr++) {
            int row = warp * 8 + rr;
            float m_ = mu[row], r_ = rs[row];
            const float4* pr = (const float4*)(g_slots + row * CC) + lane * 2;
            const float4* wq = (const float4*)g_wqbk + lane * 2;
            const float4* g4 = (const float4*)sg + lane * 2;
            const float4* b4 = (const float4*)sb + lane * 2;
            float acc = 0.f;
            #pragma unroll
            for (int h = 0; h < 2; h++) {
                float4 v = pr[h], w = wq[h], g = g4[h], bb = b4[h];
                acc += ((v.x - m_) * r_ * g.x + bb.x) * w.x
                     + ((v.y - m_) * r_ * g.y + bb.y) * w.y
                     + ((v.z - m_) * r_ * g.z + bb.z) * w.z
                     + ((v.w - m_) * r_ * g.w + bb.w) * w.w;
            }
            #pragma unroll
            for (int off = 16; off; off >>= 1)
                acc += __shfl_xor_sync(0xffffffffu, acc, off);
            if (lane == 0) g_qb[row] = acc + g_bqbk;
        }
    }

    // main: work item (row, cl)
    #pragma unroll
    for (int rep = 0; rep < 2; rep++) {
        int p = rep * 256 + tid;
        int row = p >> 3, cl = p & 7;
        float m_ = mu[row], r_ = rs[row];
        const float4* sp = (const float4*)(g_slots + row * CC);
        const float4* w4 = (const float4*)(sM + cl * 260);
        const float4* g4 = (const float4*)sg;
        const float4* b4 = (const float4*)sb;
        float acc = g_qtb[c0 + cl];
        #pragma unroll 8
        for (int i = 0; i < 64; i++) {
            float4 v = sp[i], w = w4[i], g = g4[i], bb = b4[i];
            acc += ((v.x - m_) * r_ * g.x + bb.x) * w.x
                 + ((v.y - m_) * r_ * g.y + bb.y) * w.y
                 + ((v.z - m_) * r_ * g.z + bb.z) * w.z
                 + ((v.w - m_) * r_ * g.w + bb.w) * w.w;
        }
        g_qt[row * CC + c0 + cl] = acc;
    }
}

// ---------------- K3b: streaming attention pass over fp16 xnl ----------------
// grid 512 (b*32+tile of 128 tokens), block 256; warp: 16 tokens, 4 in flight
__global__ void __launch_bounds__(256, 2) k_attn() {
    __shared__ __align__(16) float racc[8][KK][CC];
    __shared__ float racs[8][KK];
    int b = blockIdx.x >> 5;
    int tile = blockIdx.x & 31;
    int warp = threadIdx.x >> 5;
    int lane = threadIdx.x & 31;
    int tid = threadIdx.x;

    float4 qr[KK][2];
    float qbv[KK];
    #pragma unroll
    for (int k = 0; k < KK; k++) {
        const float4* qp = (const float4*)(g_qt + (b * KK + k) * CC) + lane * 2;
        qr[k][0] = qp[0]; qr[k][1] = qp[1];
        qbv[k] = g_qb[b * KK + k];
    }

    float acc[KK][8];
    float ssum[KK];
    #pragma unroll
    for (int k = 0; k < KK; k++) {
        ssum[k] = 0.f;
        #pragma unroll
        for (int j = 0; j < 8; j++) acc[k][j] = 0.f;
    }

    int n0 = tile * 128 + warp * 16;
    const uint4* base = (const uint4*)(g_xnl + ((size_t)(b * HWN + n0)) * CC) + lane;

    for (int r = 0; r < 4; r++) {
        // load 4 tokens (4 LDG.128), convert to fp32
        float4 xa[4][2];
        #pragma unroll
        for (int t = 0; t < 4; t++) {
            uint4 u = base[(r * 4 + t) * (CC / 8)];
            const __half2* hp = (const __half2*)&u;
            float2 f0 = __half22float2(hp[0]);
            float2 f1 = __half22float2(hp[1]);
            float2 f2 = __half22float2(hp[2]);
            float2 f3 = __half22float2(hp[3]);
            xa[t][0] = make_float4(f0.x, f0.y, f1.x, f1.y);
            xa[t][1] = make_float4(f2.x, f2.y, f3.x, f3.y);
        }
        float part[4][KK];
        #pragma unroll
        for (int t = 0; t < 4; t++) {
            #pragma unroll
            for (int k = 0; k < KK; k++) {
                part[t][k] = xa[t][0].x * qr[k][0].x + xa[t][0].y * qr[k][0].y
                           + xa[t][0].z * qr[k][0].z + xa[t][0].w * qr[k][0].w
                           + xa[t][1].x * qr[k][1].x + xa[t][1].y * qr[k][1].y
                           + xa[t][1].z * qr[k][1].z + xa[t][1].w * qr[k][1].w;
            }
        }
        #pragma unroll
        for (int t = 0; t < 4; t++) {
            float l0, l1, l2, l3;
            reduce4_warp(part[t][0], part[t][1], part[t][2], part[t][3],
                         l0, l1, l2, l3, lane);
            l0 += qbv[0]; l1 += qbv[1]; l2 += qbv[2]; l3 += qbv[3];
            float mx = fmaxf(fmaxf(l0, l1), fmaxf(l2, l3));
            float e0 = __expf(l0 - mx), e1 = __expf(l1 - mx);
            float e2 = __expf(l2 - mx), e3 = __expf(l3 - mx);
            float inv = __fdividef(1.0f, e0 + e1 + e2 + e3);
            float a[KK] = {e0 * inv, e1 * inv, e2 * inv, e3 * inv};
            #pragma unroll
            for (int k = 0; k < KK; k++) {
                ssum[k] += a[k];
                acc[k][0] += a[k] * xa[t][0].x; acc[k][1] += a[k] * xa[t][0].y;
                acc[k][2] += a[k] * xa[t][0].z; acc[k][3] += a[k] * xa[t][0].w;
                acc[k][4] += a[k] * xa[t][1].x; acc[k][5] += a[k] * xa[t][1].y;
                acc[k][6] += a[k] * xa[t][1].z; acc[k][7] += a[k] * xa[t][1].w;
            }
        }
    }

    #pragma unroll
    for (int k = 0; k < KK; k++) {
        float4* dst = (float4*)&racc[warp][k][lane * 8];
        dst[0] = make_float4(acc[k][0], acc[k][1], acc[k][2], acc[k][3]);
        dst[1] = make_float4(acc[k][4], acc[k][5], acc[k][6], acc[k][7]);
    }
    if (lane == 0) {
        #pragma unroll
        for (int k = 0; k < KK; k++) racs[warp][k] = ssum[k];
    }
    __syncthreads();

    #pragma unroll
    for (int k = 0; k < KK; k++) {
        float s = 0.f;
        #pragma unroll
        for (int w = 0; w < 8; w++) s += racc[w][k][tid];
        atomicAdd(&g_A[(b * KK + k) * CC + tid], s);
    }
    if (tid < KK) {
        float s = 0.f;
        #pragma unroll
        for (int w = 0; w < 8; w++) s += racs[w][tid];
        atomicAdd(&g_S[b * KK + tid], s);
    }
}

// ---------------- K3c: spre = prev@Wu1^T + (A/(S+e))@Wvu^T + b*bvu + bu + prev ------
__global__ void __launch_bounds__(256) k_spre2(const float* __restrict__ Wu,
                                               const float* __restrict__ bu) {
    __shared__ __align__(16) float sw1[8 * 260];
    __shared__ __align__(16) float swv[8 * 260];
    int d0 = blockIdx.x * 8;
    int tid = threadIdx.x;
    #pragma unroll
    for (int it = 0; it < 8; it++) {
        int idx = it * 256 + tid;
        int r = idx >> 8, c = idx & 255;
        sw1[r * 260 + c] = Wu[(size_t)(d0 + r) * 512 + c];
        swv[r * 260 + c] = g_Wvu[(size_t)(d0 + r) * CC + c];
    }
    __syncthreads();
    #pragma unroll
    for (int rep = 0; rep < 2; rep++) {
        int p = rep * 256 + tid;
        int row = p >> 3, dl = p & 7;
        int d = d0 + dl;
        float S = g_S[row];
        float inv = 1.0f / (S + EPS_W);
        float beta = S * inv;
        const float4* pr = (const float4*)(g_slots + row * CC);
        const float4* a4 = (const float4*)(g_A + row * CC);
        const float4* w1 = (const float4*)(sw1 + dl * 260);
        const float4* wv = (const float4*)(swv + dl * 260);
        float acc = bu[d] + g_slots[row * CC + d] + beta * g_bvu[d];
        float accA = 0.f;
        #pragma unroll 8
        for (int i = 0; i < 64; i++) {
            float4 a = pr[i], w = w1[i];
            acc += a.x * w.x + a.y * w.y + a.z * w.z + a.w * w.w;
            float4 u = a4[i], vv = wv[i];
            accA += u.x * vv.x + u.y * vv.y + u.z * vv.z + u.w * vv.w;
        }
        g_spre[row * CC + d] = acc + inv * accA;
    }
}

// ---------------- K3d: h = gelu(LN(spre) @ W1^T + b1), LN fused ----------------
__global__ void __launch_bounds__(256) k_hid(const float* __restrict__ W1,
                                             const float* __restrict__ b1,
                                             const float* __restrict__ lg,
                                             const float* __restrict__ lb) {
    __shared__ __align__(16) float sw[8 * 260];
    __shared__ __align__(16) float slg[CC], slb[CC];
    __shared__ float mu[64], rs[64];
    int j0 = blockIdx.x * 8;
    int tid = threadIdx.x;
    int warp = tid >> 5, lane = tid & 31;

    #pragma unroll
    for (int it = 0; it < 8; it++) {
        int idx = it * 256 + tid;
        sw[(idx >> 8) * 260 + (idx & 255)] = W1[(size_t)j0 * CC + idx];
    }
    slg[tid] = lg[tid];
    slb[tid] = lb[tid];

    #pragma unroll
    for (int rr = 0; rr < 8; rr++) {
        int row = warp * 8 + rr;
        const float4* pr = (const float4*)(g_spre + row * CC) + lane * 2;
        float4 v0 = pr[0], v1 = pr[1];
        float s = v0.x + v0.y + v0.z + v0.w + v1.x + v1.y + v1.z + v1.w;
        float q = v0.x * v0.x + v0.y * v0.y + v0.z * v0.z + v0.w * v0.w
                + v1.x * v1.x + v1.y * v1.y + v1.z * v1.z + v1.w * v1.w;
        #pragma unroll
        for (int off = 16; off; off >>= 1) {
            s += __shfl_xor_sync(0xffffffffu, s, off);
            q += __shfl_xor_sync(0xffffffffu, q, off);
        }
        if (lane == 0) {
            float m = s * (1.0f / 256.0f);
            mu[row] = m;
            rs[row] = rsqrtf(q * (1.0f / 256.0f) - m * m + LN_EPS);
        }
    }
    __syncthreads();

    #pragma unroll
    for (int rep = 0; rep < 2; rep++) {
        int p = rep * 256 + tid;
        int row = p >> 3, jl = p & 7;
        float m_ = mu[row], r_ = rs[row];
        const float4* sp = (const float4*)(g_spre + row * CC);
        const float4* w4 = (const float4*)(sw + jl * 260);
        const float4* g4 = (const float4*)slg;
        const float4* b4 = (const float4*)slb;
        float acc = b1[j0 + jl];
        #pragma unroll 8
        for (int i = 0; i < 64; i++) {
            float4 v = sp[i], w = w4[i], g = g4[i], bb = b4[i];
            acc += ((v.x - m_) * r_ * g.x + bb.x) * w.x
                 + ((v.y - m_) * r_ * g.y + bb.y) * w.y
                 + ((v.z - m_) * r_ * g.z + bb.z) * w.z
                 + ((v.w - m_) * r_ * g.w + bb.w) * w.w;
        }
        g_h[row * HIDN + j0 + jl] = gelu_f(acc);
    }
}

// ---------------- K3e: slots = spre + h @ W2^T + b2 ----------------
__global__ void __launch_bounds__(256) k_outp(const float* __restrict__ W2,
                                              const float* __restrict__ b2) {
    __shared__ __align__(16) float sw[8 * 516];
    int d0 = blockIdx.x * 8;
    int tid = threadIdx.x;
    #pragma unroll
    for (int it = 0; it < 16; it++) {
        int idx = it * 256 + tid;
        sw[(idx >> 9) * 516 + (idx & 511)] = W2[(size_t)d0 * HIDN + idx];
    }
    __syncthreads();
    #pragma unroll
    for (int rep = 0; rep < 2; rep++) {
        int p = rep * 256 + tid;
        int row = p >> 3, dl = p & 7;
        int d = d0 + dl;
        const float4* h4 = (const float4*)(g_h + row * HIDN);
        const float4* w4 = (const float4*)(sw + dl * 516);
        float acc = b2[d] + g_spre[row * CC + d];
        #pragma unroll 8
        for (int i = 0; i < 128; i++) {
            float4 a = h4[i], w = w4[i];
            acc += a.x * w.x + a.y * w.y + a.z * w.z + a.w * w.w;
        }
        g_slots[row * CC + d] = acc;
    }
}

// ---------------- K4: final head + output write ----------------
__global__ void __launch_bounds__(128) k_final(const float* __restrict__ We1,
                                               const float* __restrict__ be1,
                                               const float* __restrict__ We2,
                                               const float* __restrict__ be2,
                                               float* __restrict__ out) {
    __shared__ __align__(16) float s[CC];
    __shared__ float red[128];
    int row = blockIdx.x, tid = threadIdx.x;
    float v0 = g_slots[row * CC + tid];
    float v1 = g_slots[row * CC + tid + 128];
    s[tid] = v0; s[tid + 128] = v1;
    out[row * CC + tid] = v0;
    out[row * CC + tid + 128] = v1;
    __syncthreads();

    const float4* w4 = (const float4*)(We1 + (size_t)tid * CC);
    const float4* s4 = (const float4*)s;
    float acc = be1[tid];
    #pragma unroll 8
    for (int i = 0; i < 64; i++) {
        float4 a = s4[i], w = w4[i];
        acc += a.x * w.x + a.y * w.y + a.z * w.z + a.w * w.w;
    }
    float e = gelu_f(acc);
    red[tid] = e * We2[tid];
    __syncthreads();
    #pragma unroll
    for (int st = 64; st > 0; st >>= 1) {
        if (tid < st) red[tid] += red[tid + st];
        __syncthreads();
    }
    if (tid == 0) {
        float z = red[0] + be2[0];
        out[BB * KK * CC + row] = 1.0f / (1.0f + expf(-z));
    }
}

// ---------------- host ----------------
extern "C" void kernel_launch(void* const* d_in, const int* in_sizes, int n_in,
                              void* d_out, int out_size) {
    const float* x        = (const float*)d_in[0];
    const float* noise    = (const float*)d_in[1];
    const float* slot_mu  = (const float*)d_in[2];
    const float* slot_ls  = (const float*)d_in[3];
    const float* ln_in_g  = (const float*)d_in[4];
    const float* ln_in_b  = (const float*)d_in[5];
    const float* ln_sl_g  = (const float*)d_in[6];
    const float* ln_sl_b  = (const float*)d_in[7];
    const float* ln_mlp_g = (const float*)d_in[8];
    const float* ln_mlp_b = (const float*)d_in[9];
    const float* Wq = (const float*)d_in[10];
    const float* bq = (const float*)d_in[11];
    const float* Wk = (const float*)d_in[12];
    const float* bk = (const float*)d_in[13];
    const float* Wv = (const float*)d_in[14];
    const float* bv = (const float*)d_in[15];
    const float* Wu = (const float*)d_in[16];
    const float* bu = (const float*)d_in[17];
    const float* W1 = (const float*)d_in[18];
    const float* b1 = (const float*)d_in[19];
    const float* W2 = (const float*)d_in[20];
    const float* b2 = (const float*)d_in[21];
    const float* We1 = (const float*)d_in[22];
    const float* be1 = (const float*)d_in[23];
    const float* We2 = (const float*)d_in[24];
    const float* be2 = (const float*)d_in[25];
    float* out = (float*)d_out;

    k_prep<<<64, 256>>>(Wu, Wv, bv);
    k_prep2<<<65, 256>>>(Wq, Wk, bq, bk);
    k_ln_input<<<2048, 256>>>(x, ln_in_g, ln_in_b);
    k_init_slots<<<64, 256>>>(slot_mu, slot_ls, noise);

    for (int it = 0; it < 3; it++) {
        k_qt<<<32, 256>>>(ln_sl_g, ln_sl_b);
        k_attn<<<512, 256>>>();
        k_spre2<<<32, 256>>>(Wu, bu);
        k_hid<<<64, 256>>>(W1, b1, ln_mlp_g, ln_mlp_b);
        k_outp<<<32, 256>>>(W2, b2);
    }

    k_final<<<64, 128>>>(We1, be1, We2, be2, out);
}